// round 2
// baseline (speedup 1.0000x reference)
#include <cuda_runtime.h>

#define VOL 262144   // 64*64*64 voxels

// ---------------- device-global precomputed weights (scratch; no allocs) ----------------
__device__ __align__(16) float g_WQKV[384 * 128];  // folded qkv weights: [o][c] c<64 conv path, c>=64 trans path
__device__ float g_QB[384];                        // folded qkv bias
__device__ __align__(16) float g_P[64 * 128];      // proj_w[:64] + proj_w[64:]
__device__ float g_PB[64];                         // proj_b[:64] + proj_b[64:]
__device__ __align__(16) float g_BIAS[4 * 64 * 64];// dense rel-pos bias [h][i][j]

// ---------------- prep kernel: fold weights, gather bias table ----------------
__global__ void prep_kernel(const float* __restrict__ conv_w, const float* __restrict__ conv_b,
                            const float* __restrict__ trans_w, const float* __restrict__ trans_b,
                            const float* __restrict__ qkv_w, const float* __restrict__ qkv_b,
                            const float* __restrict__ proj_w, const float* __restrict__ proj_b,
                            const float* __restrict__ table, const int* __restrict__ ridx)
{
    int id = blockIdx.x * blockDim.x + threadIdx.x;
    if (id < 49152) {                       // WQKV[o][c] = sum_m qkv_w[o][m or 64+m] * {conv,trans}_w[m][c]
        int o = id >> 7, c = id & 127;
        float s = 0.f;
        if (c < 64) {
            const float* qw = qkv_w + o * 128;
            #pragma unroll 8
            for (int m = 0; m < 64; m++) s += qw[m] * conv_w[m * 64 + c];
        } else {
            const float* qw = qkv_w + o * 128 + 64;
            int cc = c - 64;
            #pragma unroll 8
            for (int m = 0; m < 64; m++) s += qw[m] * trans_w[m * 64 + cc];
        }
        g_WQKV[id] = s;
    } else if (id < 49536) {                // QB
        int o = id - 49152;
        float s = qkv_b[o];
        const float* qw = qkv_w + o * 128;
        #pragma unroll 8
        for (int m = 0; m < 64; m++) s += qw[m] * conv_b[m] + qw[64 + m] * trans_b[m];
        g_QB[o] = s;
    } else if (id < 57728) {                // P
        int p = id - 49536;
        int c = p >> 7, k = p & 127;
        g_P[p] = proj_w[c * 128 + k] + proj_w[(c + 64) * 128 + k];
    } else if (id < 57792) {                // PB
        int c = id - 57728;
        g_PB[c] = proj_b[c] + proj_b[c + 64];
    } else if (id < 74176) {                // BIAS[h][i][j] = table[ridx[i*64+j]][h]
        int x = id - 57792;
        int h = x >> 12, ij = x & 4095;
        g_BIAS[x] = table[ridx[ij] * 4 + h];
    }
}

// ---------------- fused per-window kernel ----------------
// smem layout (floats):
//   feat : [128][68]           off 0      (cf rows 0..63 kept for residual, tf rows 64..127)
//   qkv  : 64 tokens * 96 16B-units, XOR-swizzled        off 8704
//   wt   : [c:128][o:132] transposed weight tile          off 33280 (spans to 50176)
//   outs : [64][129]  (aliases wt)                        off 33280
//   ps   : [64][132]  (aliases wt upper half)             off 41728
// total 50176 floats = 200704 bytes

__global__ void __launch_bounds__(256, 1)
fused_attn_kernel(const float* __restrict__ conv_feat,
                  const float* __restrict__ trans_feat,
                  float* __restrict__ out)
{
    extern __shared__ float sm[];
    float* feat = sm;
    float* qkvs = sm + 8704;
    float* wt   = sm + 33280;
    float* outs = sm + 33280;
    float* ps   = sm + 41728;

    const int tid = threadIdx.x;
    const int wb = blockIdx.x;
    const int base = ((wb >> 8) * 4) * 4096 + (((wb >> 4) & 15) * 4) * 64 + (wb & 15) * 4;

    // ---- Phase 1: load cf/tf window tiles (channel-major [c][t]) ----
    #pragma unroll
    for (int k = 0; k < 8; k++) {
        int v = k * 256 + tid;              // 0..2047 float4s
        int vv = v & 1023;
        int c = vv >> 4;
        int r16 = vv & 15;                  // (dz,dy)
        const float* src = (v < 1024) ? conv_feat : trans_feat;
        float4 val = *(const float4*)(src + (size_t)c * VOL + base + (r16 >> 2) * 4096 + (r16 & 3) * 64);
        int row = (v < 1024) ? c : (64 + c);
        *(float4*)(feat + row * 68 + r16 * 4) = val;
    }
    __syncthreads();

    // ---- Phase 2: qkv[t][o] = sum_c WQKV[o][c] * feat[c][t] + QB[o] ----
    const int tx = tid & 15;   // t-group (4 tokens)
    const int ty = tid >> 4;   // o-group (8 outputs per 128-chunk)
    float4* qkv4 = (float4*)qkvs;
    const int sx = tx & 7;     // swizzle key = (t>>2)&7

    for (int ob = 0; ob < 384; ob += 128) {
        // stage weight chunk transposed: wt[c][o_local], stride 132
        #pragma unroll
        for (int k = 0; k < 16; k++) {
            int f = k * 256 + tid;          // float4 index over chunk, c-fastest
            float4 wv = *((const float4*)g_WQKV + ob * 32 + f);
            int o = f >> 5, c4 = f & 31;
            wt[(c4 * 4 + 0) * 132 + o] = wv.x;
            wt[(c4 * 4 + 1) * 132 + o] = wv.y;
            wt[(c4 * 4 + 2) * 132 + o] = wv.z;
            wt[(c4 * 4 + 3) * 132 + o] = wv.w;
        }
        __syncthreads();

        float acc[8][4];
        #pragma unroll
        for (int r = 0; r < 8; r++) {
            float qb = g_QB[ob + ty * 8 + r];
            acc[r][0] = qb; acc[r][1] = qb; acc[r][2] = qb; acc[r][3] = qb;
        }
        #pragma unroll 8
        for (int c = 0; c < 128; c++) {
            float4 fv = *(const float4*)(feat + c * 68 + tx * 4);
            #pragma unroll
            for (int r = 0; r < 8; r++) {
                float w = wt[c * 132 + ty * 8 + r];
                acc[r][0] = fmaf(w, fv.x, acc[r][0]);
                acc[r][1] = fmaf(w, fv.y, acc[r][1]);
                acc[r][2] = fmaf(w, fv.z, acc[r][2]);
                acc[r][3] = fmaf(w, fv.w, acc[r][3]);
            }
        }
        // swizzled conflict-free float4 stores along o
        #pragma unroll
        for (int r4 = 0; r4 < 2; r4++) {
            int u = (ob >> 2) + ty * 2 + r4;  // 16B-unit index within 96
            #pragma unroll
            for (int m = 0; m < 4; m++) {
                int t = tx * 4 + m;
                qkv4[t * 96 + (u ^ sx)] =
                    make_float4(acc[r4 * 4 + 0][m], acc[r4 * 4 + 1][m],
                                acc[r4 * 4 + 2][m], acc[r4 * 4 + 3][m]);
            }
        }
        __syncthreads();
    }

    // ---- Phase 3: per-(head,row) attention entirely in registers ----
    {
        const int h = tid >> 6;            // warp-uniform
        const int ii = tid & 63;
        const int isw = (ii >> 2) & 7;
        float qv[32];
        #pragma unroll
        for (int d4 = 0; d4 < 8; d4++) {
            float4 q4 = qkv4[ii * 96 + ((h * 8 + d4) ^ isw)];
            qv[d4 * 4 + 0] = q4.x; qv[d4 * 4 + 1] = q4.y;
            qv[d4 * 4 + 2] = q4.z; qv[d4 * 4 + 3] = q4.w;
        }
        float sc[64];
        const float4* brow4 = (const float4*)(g_BIAS + (h * 64 + ii) * 64);
        #pragma unroll
        for (int j4 = 0; j4 < 16; j4++) {
            float4 b = brow4[j4];
            sc[j4 * 4 + 0] = b.x; sc[j4 * 4 + 1] = b.y;
            sc[j4 * 4 + 2] = b.z; sc[j4 * 4 + 3] = b.w;
        }
        const float scale = 0.17677669529663688f;  // 32^-0.5
        float rowmax = -1e30f;
        #pragma unroll
        for (int j = 0; j < 64; j++) {
            int jsw = (j >> 2) & 7;
            float a = 0.f;
            #pragma unroll
            for (int d4 = 0; d4 < 8; d4++) {
                float4 k4 = qkv4[j * 96 + ((32 + h * 8 + d4) ^ jsw)];  // warp-broadcast
                a = fmaf(qv[d4 * 4 + 0], k4.x, a);
                a = fmaf(qv[d4 * 4 + 1], k4.y, a);
                a = fmaf(qv[d4 * 4 + 2], k4.z, a);
                a = fmaf(qv[d4 * 4 + 3], k4.w, a);
            }
            sc[j] = fmaf(a, scale, sc[j]);
            rowmax = fmaxf(rowmax, sc[j]);
        }
        float ssum = 0.f;
        #pragma unroll
        for (int j = 0; j < 64; j++) {
            sc[j] = __expf(sc[j] - rowmax);
            ssum += sc[j];
        }
        float inv = 1.f / ssum;
        float ov[32];
        #pragma unroll
        for (int d = 0; d < 32; d++) ov[d] = 0.f;
        #pragma unroll
        for (int j = 0; j < 64; j++) {
            int jsw = (j >> 2) & 7;
            float p = sc[j];
            #pragma unroll
            for (int d4 = 0; d4 < 8; d4++) {
                float4 v4 = qkv4[j * 96 + ((64 + h * 8 + d4) ^ jsw)];  // warp-broadcast
                ov[d4 * 4 + 0] = fmaf(p, v4.x, ov[d4 * 4 + 0]);
                ov[d4 * 4 + 1] = fmaf(p, v4.y, ov[d4 * 4 + 1]);
                ov[d4 * 4 + 2] = fmaf(p, v4.z, ov[d4 * 4 + 2]);
                ov[d4 * 4 + 3] = fmaf(p, v4.w, ov[d4 * 4 + 3]);
            }
        }
        #pragma unroll
        for (int d = 0; d < 32; d++) outs[ii * 129 + h * 32 + d] = ov[d] * inv;
    }

    // stage P tile (aliases wt upper half; disjoint from outs & qkv — no sync needed yet)
    #pragma unroll
    for (int k = 0; k < 8; k++) {
        int f = k * 256 + tid;
        float4 pv = *((const float4*)g_P + f);
        *(float4*)(ps + (f >> 5) * 132 + (f & 31) * 4) = pv;
    }
    __syncthreads();

    // ---- Phase 4: final[t][c] = sum_k outs[t][k]*P[c][k] + PB[c] + conv_feat[c][t] ----
    {
        float acc2[4][4];
        #pragma unroll
        for (int r = 0; r < 4; r++)
            #pragma unroll
            for (int m = 0; m < 4; m++) acc2[r][m] = 0.f;

        #pragma unroll 4
        for (int k = 0; k < 128; k++) {
            float pv[4], ovv[4];
            #pragma unroll
            for (int r = 0; r < 4; r++) pv[r] = ps[(ty * 4 + r) * 132 + k];
            #pragma unroll
            for (int m = 0; m < 4; m++) ovv[m] = outs[(tx * 4 + m) * 129 + k];
            #pragma unroll
            for (int r = 0; r < 4; r++)
                #pragma unroll
                for (int m = 0; m < 4; m++)
                    acc2[r][m] = fmaf(pv[r], ovv[m], acc2[r][m]);
        }
        int dz = tx >> 2, dy = tx & 3;
        #pragma unroll
        for (int r = 0; r < 4; r++) {
            int c = ty * 4 + r;
            float pb = g_PB[c];
            float4 cf = *(const float4*)(feat + c * 68 + tx * 4);
            float4 res;
            res.x = acc2[r][0] + pb + cf.x;
            res.y = acc2[r][1] + pb + cf.y;
            res.z = acc2[r][2] + pb + cf.z;
            res.w = acc2[r][3] + pb + cf.w;
            *(float4*)(out + (size_t)c * VOL + base + dz * 4096 + dy * 64) = res;
        }
    }
}

// ---------------- launch ----------------
extern "C" void kernel_launch(void* const* d_in, const int* in_sizes, int n_in,
                              void* d_out, int out_size)
{
    const float* conv_feat  = (const float*)d_in[0];
    const float* trans_feat = (const float*)d_in[1];
    const float* conv_w     = (const float*)d_in[2];
    const float* conv_b     = (const float*)d_in[3];
    const float* trans_w    = (const float*)d_in[4];
    const float* trans_b    = (const float*)d_in[5];
    const float* qkv_w      = (const float*)d_in[6];
    const float* qkv_b      = (const float*)d_in[7];
    const float* proj_w     = (const float*)d_in[8];
    const float* proj_b     = (const float*)d_in[9];
    const float* table      = (const float*)d_in[10];
    const int*   ridx       = (const int*)d_in[11];
    float* o = (float*)d_out;

    cudaFuncSetAttribute(fused_attn_kernel, cudaFuncAttributeMaxDynamicSharedMemorySize, 200704);

    prep_kernel<<<290, 256>>>(conv_w, conv_b, trans_w, trans_b,
                              qkv_w, qkv_b, proj_w, proj_b, table, ridx);
    fused_attn_kernel<<<4096, 256, 200704>>>(conv_feat, trans_feat, o);
}

// round 3
// speedup vs baseline: 1.9755x; 1.9755x over previous
#include <cuda_runtime.h>

#define VOL 262144   // 64*64*64 voxels

// ---------------- device-global precomputed weights (scratch; no allocs) ----------------
__device__ __align__(16) float g_WQKVT[128 * 384]; // folded qkv weights TRANSPOSED: [c][o]
__device__ float g_QB[384];                        // folded qkv bias
__device__ __align__(16) float g_P[64 * 128];      // proj_w[:64] + proj_w[64:]  [c][k]
__device__ float g_PB[64];                         // proj_b[:64] + proj_b[64:]
__device__ __align__(16) float g_BIAS[4 * 64 * 64];// dense rel-pos bias [h][i][j]

// ---------------- prep kernel: fold weights, gather bias table ----------------
__global__ void prep_kernel(const float* __restrict__ conv_w, const float* __restrict__ conv_b,
                            const float* __restrict__ trans_w, const float* __restrict__ trans_b,
                            const float* __restrict__ qkv_w, const float* __restrict__ qkv_b,
                            const float* __restrict__ proj_w, const float* __restrict__ proj_b,
                            const float* __restrict__ table, const int* __restrict__ ridx)
{
    int id = blockIdx.x * blockDim.x + threadIdx.x;
    if (id < 49152) {                       // WQKVT[c][o] = sum_m qkv_w[o][m or 64+m] * {conv,trans}_w[m][c]
        int c = id / 384, o = id % 384;
        float s = 0.f;
        if (c < 64) {
            const float* qw = qkv_w + o * 128;
            #pragma unroll 8
            for (int m = 0; m < 64; m++) s += qw[m] * conv_w[m * 64 + c];
        } else {
            const float* qw = qkv_w + o * 128 + 64;
            int cc = c - 64;
            #pragma unroll 8
            for (int m = 0; m < 64; m++) s += qw[m] * trans_w[m * 64 + cc];
        }
        g_WQKVT[id] = s;
    } else if (id < 49536) {                // QB
        int o = id - 49152;
        float s = qkv_b[o];
        const float* qw = qkv_w + o * 128;
        #pragma unroll 8
        for (int m = 0; m < 64; m++) s += qw[m] * conv_b[m] + qw[64 + m] * trans_b[m];
        g_QB[o] = s;
    } else if (id < 57728) {                // P[c][k]
        int p = id - 49536;
        int c = p >> 7, k = p & 127;
        g_P[p] = proj_w[c * 128 + k] + proj_w[(c + 64) * 128 + k];
    } else if (id < 57792) {                // PB
        int c = id - 57728;
        g_PB[c] = proj_b[c] + proj_b[c + 64];
    } else if (id < 74176) {                // BIAS[h][i][j] = table[ridx[i*64+j]][h]
        int x = id - 57792;
        int h = x >> 12, ij = x & 4095;
        g_BIAS[x] = table[ridx[ij] * 4 + h];
    }
}

// ---------------- fused per-window kernel ----------------
// smem layout (floats):
//   feat : [128][68]                                      off 0
//   qkv  : 64 tokens * 96 16B-units, XOR-swizzled         off 8704
//   wt   : [c:128] x 33 float4 (o-vectorized)             off 33280 (spans to 50176)
//   outs : [64] x 33 float4 (aliases wt lower half)       off 33280
//   ps   : [64] x 33 float4 (aliases wt upper half)       off 41728
// total 50176 floats = 200704 bytes

__global__ void __launch_bounds__(256, 1)
fused_attn_kernel(const float* __restrict__ conv_feat,
                  const float* __restrict__ trans_feat,
                  float* __restrict__ out)
{
    extern __shared__ float sm[];
    float* feat = sm;
    float4* feat4 = (float4*)sm;           // stride 17 float4 per row
    float4* qkv4  = (float4*)(sm + 8704);  // stride 96 float4 per token
    float4* wt4   = (float4*)(sm + 33280); // stride 33 float4 per c
    float4* outs4 = (float4*)(sm + 33280); // stride 33 float4 per token
    float4* ps4   = (float4*)(sm + 41728); // stride 33 float4 per channel
    float* outsf  = sm + 33280;

    const int tid = threadIdx.x;
    const int wb = blockIdx.x;
    const int base = ((wb >> 8) * 4) * 4096 + (((wb >> 4) & 15) * 4) * 64 + (wb & 15) * 4;

    // ---- Phase 1: load cf/tf window tiles (channel-major [c][t]) ----
    #pragma unroll
    for (int k = 0; k < 8; k++) {
        int v = k * 256 + tid;              // 0..2047 float4s
        int vv = v & 1023;
        int c = vv >> 4;
        int r16 = vv & 15;                  // (dz,dy)
        const float* src = (v < 1024) ? conv_feat : trans_feat;
        float4 val = *(const float4*)(src + (size_t)c * VOL + base + (r16 >> 2) * 4096 + (r16 & 3) * 64);
        int row = (v < 1024) ? c : (64 + c);
        feat4[row * 17 + r16] = val;
    }
    __syncthreads();

    // ---- Phase 2: qkv[t][o] = sum_c WQKVT[c][o] * feat[c][t] + QB[o] ----
    const int tx = tid & 15;   // token group (4 tokens: t = tx*4+m)
    const int ty = tid >> 4;   // output group (8 outputs: o = ob + ty*8 + r)
    const int sx = tx & 7;     // swizzle key = (t>>2)&7
    const float4* gW4 = (const float4*)g_WQKVT;  // [c][96] float4

    for (int ob = 0; ob < 384; ob += 128) {
        // stage weight chunk: wt4[c*33 + o4] = WQKVT4[c*96 + ob/4 + o4]
        #pragma unroll
        for (int k = 0; k < 16; k++) {
            int f = k * 256 + tid;          // 0..4095
            int c = f >> 5, o4 = f & 31;
            wt4[c * 33 + o4] = gW4[c * 96 + (ob >> 2) + o4];
        }
        __syncthreads();

        float acc[8][4];
        #pragma unroll
        for (int r = 0; r < 8; r++) {
            float qb = g_QB[ob + ty * 8 + r];
            acc[r][0] = qb; acc[r][1] = qb; acc[r][2] = qb; acc[r][3] = qb;
        }
        #pragma unroll 4
        for (int c = 0; c < 128; c++) {
            float4 fv = feat4[c * 17 + tx];
            float4 w0 = wt4[c * 33 + ty * 2];
            float4 w1 = wt4[c * 33 + ty * 2 + 1];
            acc[0][0] = fmaf(w0.x, fv.x, acc[0][0]); acc[0][1] = fmaf(w0.x, fv.y, acc[0][1]);
            acc[0][2] = fmaf(w0.x, fv.z, acc[0][2]); acc[0][3] = fmaf(w0.x, fv.w, acc[0][3]);
            acc[1][0] = fmaf(w0.y, fv.x, acc[1][0]); acc[1][1] = fmaf(w0.y, fv.y, acc[1][1]);
            acc[1][2] = fmaf(w0.y, fv.z, acc[1][2]); acc[1][3] = fmaf(w0.y, fv.w, acc[1][3]);
            acc[2][0] = fmaf(w0.z, fv.x, acc[2][0]); acc[2][1] = fmaf(w0.z, fv.y, acc[2][1]);
            acc[2][2] = fmaf(w0.z, fv.z, acc[2][2]); acc[2][3] = fmaf(w0.z, fv.w, acc[2][3]);
            acc[3][0] = fmaf(w0.w, fv.x, acc[3][0]); acc[3][1] = fmaf(w0.w, fv.y, acc[3][1]);
            acc[3][2] = fmaf(w0.w, fv.z, acc[3][2]); acc[3][3] = fmaf(w0.w, fv.w, acc[3][3]);
            acc[4][0] = fmaf(w1.x, fv.x, acc[4][0]); acc[4][1] = fmaf(w1.x, fv.y, acc[4][1]);
            acc[4][2] = fmaf(w1.x, fv.z, acc[4][2]); acc[4][3] = fmaf(w1.x, fv.w, acc[4][3]);
            acc[5][0] = fmaf(w1.y, fv.x, acc[5][0]); acc[5][1] = fmaf(w1.y, fv.y, acc[5][1]);
            acc[5][2] = fmaf(w1.y, fv.z, acc[5][2]); acc[5][3] = fmaf(w1.y, fv.w, acc[5][3]);
            acc[6][0] = fmaf(w1.z, fv.x, acc[6][0]); acc[6][1] = fmaf(w1.z, fv.y, acc[6][1]);
            acc[6][2] = fmaf(w1.z, fv.z, acc[6][2]); acc[6][3] = fmaf(w1.z, fv.w, acc[6][3]);
            acc[7][0] = fmaf(w1.w, fv.x, acc[7][0]); acc[7][1] = fmaf(w1.w, fv.y, acc[7][1]);
            acc[7][2] = fmaf(w1.w, fv.z, acc[7][2]); acc[7][3] = fmaf(w1.w, fv.w, acc[7][3]);
        }
        // swizzled conflict-free float4 stores along o
        #pragma unroll
        for (int r4 = 0; r4 < 2; r4++) {
            int u = (ob >> 2) + ty * 2 + r4;  // 16B-unit index within 96
            #pragma unroll
            for (int m = 0; m < 4; m++) {
                int t = tx * 4 + m;
                qkv4[t * 96 + (u ^ sx)] =
                    make_float4(acc[r4 * 4 + 0][m], acc[r4 * 4 + 1][m],
                                acc[r4 * 4 + 2][m], acc[r4 * 4 + 3][m]);
            }
        }
        __syncthreads();
    }

    // ---- Phase 3: per-(head,row) attention entirely in registers ----
    {
        const int h = tid >> 6;            // warp-uniform
        const int ii = tid & 63;
        const int isw = (ii >> 2) & 7;
        float qv[32];
        #pragma unroll
        for (int d4 = 0; d4 < 8; d4++) {
            float4 q4 = qkv4[ii * 96 + ((h * 8 + d4) ^ isw)];
            qv[d4 * 4 + 0] = q4.x; qv[d4 * 4 + 1] = q4.y;
            qv[d4 * 4 + 2] = q4.z; qv[d4 * 4 + 3] = q4.w;
        }
        float sc[64];
        const float4* brow4 = (const float4*)(g_BIAS + (h * 64 + ii) * 64);
        #pragma unroll
        for (int j4 = 0; j4 < 16; j4++) {
            float4 b = brow4[j4];
            sc[j4 * 4 + 0] = b.x; sc[j4 * 4 + 1] = b.y;
            sc[j4 * 4 + 2] = b.z; sc[j4 * 4 + 3] = b.w;
        }
        const float scale = 0.17677669529663688f;  // 32^-0.5
        float rowmax = -1e30f;
        #pragma unroll
        for (int j = 0; j < 64; j++) {
            int jsw = (j >> 2) & 7;
            float a = 0.f;
            #pragma unroll
            for (int d4 = 0; d4 < 8; d4++) {
                float4 k4 = qkv4[j * 96 + ((32 + h * 8 + d4) ^ jsw)];  // warp-broadcast
                a = fmaf(qv[d4 * 4 + 0], k4.x, a);
                a = fmaf(qv[d4 * 4 + 1], k4.y, a);
                a = fmaf(qv[d4 * 4 + 2], k4.z, a);
                a = fmaf(qv[d4 * 4 + 3], k4.w, a);
            }
            sc[j] = fmaf(a, scale, sc[j]);
            rowmax = fmaxf(rowmax, sc[j]);
        }
        float ssum = 0.f;
        #pragma unroll
        for (int j = 0; j < 64; j++) {
            sc[j] = __expf(sc[j] - rowmax);
            ssum += sc[j];
        }
        float inv = 1.f / ssum;
        float ov[32];
        #pragma unroll
        for (int d = 0; d < 32; d++) ov[d] = 0.f;
        #pragma unroll
        for (int j = 0; j < 64; j++) {
            int jsw = (j >> 2) & 7;
            float p = sc[j];
            #pragma unroll
            for (int d4 = 0; d4 < 8; d4++) {
                float4 v4 = qkv4[j * 96 + ((64 + h * 8 + d4) ^ jsw)];  // warp-broadcast
                ov[d4 * 4 + 0] = fmaf(p, v4.x, ov[d4 * 4 + 0]);
                ov[d4 * 4 + 1] = fmaf(p, v4.y, ov[d4 * 4 + 1]);
                ov[d4 * 4 + 2] = fmaf(p, v4.z, ov[d4 * 4 + 2]);
                ov[d4 * 4 + 3] = fmaf(p, v4.w, ov[d4 * 4 + 3]);
            }
        }
        // conflict-free float4 stores: lane-consecutive rows, odd float4 stride
        #pragma unroll
        for (int d4 = 0; d4 < 8; d4++)
            outs4[ii * 33 + h * 8 + d4] =
                make_float4(ov[d4 * 4 + 0] * inv, ov[d4 * 4 + 1] * inv,
                            ov[d4 * 4 + 2] * inv, ov[d4 * 4 + 3] * inv);
    }

    // stage P tile (ps region disjoint from outs & qkv)
    #pragma unroll
    for (int k = 0; k < 8; k++) {
        int f = k * 256 + tid;              // 0..2047
        ps4[(f >> 5) * 33 + (f & 31)] = *((const float4*)g_P + f);
    }
    __syncthreads();

    // ---- Phase 4: final[t][c] = sum_k outs[t][k]*P[c][k] + PB[c] + conv_feat[c][t] ----
    // token mapping t = m*16 + tx  (lane-consecutive -> conflict-free outs reads)
    {
        float acc2[4][4];
        #pragma unroll
        for (int r = 0; r < 4; r++)
            #pragma unroll
            for (int m = 0; m < 4; m++) acc2[r][m] = 0.f;

        #pragma unroll 4
        for (int k4 = 0; k4 < 32; k4++) {
            float4 pr[4], ovv[4];
            #pragma unroll
            for (int r = 0; r < 4; r++) pr[r] = ps4[(ty * 4 + r) * 33 + k4];
            #pragma unroll
            for (int m = 0; m < 4; m++) ovv[m] = outs4[(m * 16 + tx) * 33 + k4];
            #pragma unroll
            for (int r = 0; r < 4; r++)
                #pragma unroll
                for (int m = 0; m < 4; m++) {
                    acc2[r][m] = fmaf(pr[r].x, ovv[m].x, acc2[r][m]);
                    acc2[r][m] = fmaf(pr[r].y, ovv[m].y, acc2[r][m]);
                    acc2[r][m] = fmaf(pr[r].z, ovv[m].z, acc2[r][m]);
                    acc2[r][m] = fmaf(pr[r].w, ovv[m].w, acc2[r][m]);
                }
        }
        int dy = tx >> 2, dx = tx & 3;
        #pragma unroll
        for (int r = 0; r < 4; r++) {
            int c = ty * 4 + r;
            float pb = g_PB[c];
            #pragma unroll
            for (int m = 0; m < 4; m++) {
                int t = m * 16 + tx;
                float cf = feat[c * 68 + t];
                out[(size_t)c * VOL + base + m * 4096 + dy * 64 + dx] = acc2[r][m] + pb + cf;
            }
        }
    }
}

// ---------------- launch ----------------
extern "C" void kernel_launch(void* const* d_in, const int* in_sizes, int n_in,
                              void* d_out, int out_size)
{
    const float* conv_feat  = (const float*)d_in[0];
    const float* trans_feat = (const float*)d_in[1];
    const float* conv_w     = (const float*)d_in[2];
    const float* conv_b     = (const float*)d_in[3];
    const float* trans_w    = (const float*)d_in[4];
    const float* trans_b    = (const float*)d_in[5];
    const float* qkv_w      = (const float*)d_in[6];
    const float* qkv_b      = (const float*)d_in[7];
    const float* proj_w     = (const float*)d_in[8];
    const float* proj_b     = (const float*)d_in[9];
    const float* table      = (const float*)d_in[10];
    const int*   ridx       = (const int*)d_in[11];
    float* o = (float*)d_out;

    cudaFuncSetAttribute(fused_attn_kernel, cudaFuncAttributeMaxDynamicSharedMemorySize, 200704);

    prep_kernel<<<290, 256>>>(conv_w, conv_b, trans_w, trans_b,
                              qkv_w, qkv_b, proj_w, proj_b, table, ridx);
    fused_attn_kernel<<<4096, 256, 200704>>>(conv_feat, trans_feat, o);
}

// round 4
// speedup vs baseline: 1.9779x; 1.0012x over previous
#include <cuda_runtime.h>

#define VOL 262144   // 64*64*64 voxels

typedef unsigned long long u64;

__device__ __forceinline__ u64 pk2(float lo, float hi) {
    u64 r; asm("mov.b64 %0,{%1,%2};" : "=l"(r) : "f"(lo), "f"(hi)); return r;
}
__device__ __forceinline__ void upk2(u64 v, float& lo, float& hi) {
    asm("mov.b64 {%0,%1},%2;" : "=f"(lo), "=f"(hi) : "l"(v));
}
__device__ __forceinline__ void fma2(u64& d, u64 a, u64 b) {
    asm("fma.rn.f32x2 %0,%1,%2,%0;" : "+l"(d) : "l"(a), "l"(b));
}
__device__ __forceinline__ u64 mul2(u64 a, u64 b) {
    u64 r; asm("mul.rn.f32x2 %0,%1,%2;" : "=l"(r) : "l"(a), "l"(b)); return r;
}

// ---------------- device-global precomputed weights (scratch; no allocs) ----------------
__device__ __align__(16) float g_WQKVT[128 * 384]; // folded qkv weights TRANSPOSED: [c][o]
__device__ float g_QB[384];                        // folded qkv bias
__device__ __align__(16) float g_P[64 * 128];      // proj_w[:64] + proj_w[64:]  [c][k]
__device__ float g_PB[64];                         // proj_b[:64] + proj_b[64:]
__device__ __align__(16) float g_BIAS[4 * 64 * 64];// dense rel-pos bias [h][i][j]

// ---------------- prep kernel: fold weights, gather bias table ----------------
__global__ void prep_kernel(const float* __restrict__ conv_w, const float* __restrict__ conv_b,
                            const float* __restrict__ trans_w, const float* __restrict__ trans_b,
                            const float* __restrict__ qkv_w, const float* __restrict__ qkv_b,
                            const float* __restrict__ proj_w, const float* __restrict__ proj_b,
                            const float* __restrict__ table, const int* __restrict__ ridx)
{
    int id = blockIdx.x * blockDim.x + threadIdx.x;
    if (id < 49152) {                       // WQKVT[c][o]
        int c = id / 384, o = id % 384;
        float s = 0.f;
        if (c < 64) {
            const float* qw = qkv_w + o * 128;
            #pragma unroll 8
            for (int m = 0; m < 64; m++) s += qw[m] * conv_w[m * 64 + c];
        } else {
            const float* qw = qkv_w + o * 128 + 64;
            int cc = c - 64;
            #pragma unroll 8
            for (int m = 0; m < 64; m++) s += qw[m] * trans_w[m * 64 + cc];
        }
        g_WQKVT[id] = s;
    } else if (id < 49536) {                // QB
        int o = id - 49152;
        float s = qkv_b[o];
        const float* qw = qkv_w + o * 128;
        #pragma unroll 8
        for (int m = 0; m < 64; m++) s += qw[m] * conv_b[m] + qw[64 + m] * trans_b[m];
        g_QB[o] = s;
    } else if (id < 57728) {                // P[c][k]
        int p = id - 49536;
        int c = p >> 7, k = p & 127;
        g_P[p] = proj_w[c * 128 + k] + proj_w[(c + 64) * 128 + k];
    } else if (id < 57792) {                // PB
        int c = id - 57728;
        g_PB[c] = proj_b[c] + proj_b[c + 64];
    } else if (id < 74176) {                // BIAS[h][i][j]
        int x = id - 57792;
        int h = x >> 12, ij = x & 4095;
        g_BIAS[x] = table[ridx[ij] * 4 + h];
    }
}

// ---------------- fused per-window kernel ----------------
// smem layout (floats):
//   feat : [128] x 17 float4                              off 0
//   qkv  : 64 tokens * 96 16B-units, XOR-swizzled         off 8704
//   wt   : [c:128] x 33 float4 (o-vectorized)             off 33280 (spans to 50176)
//   outs : [64] x 33 float4 (aliases wt lower half)       off 33280
//   ps   : [64] x 33 float4 (aliases wt upper half)       off 41728
// total 50176 floats = 200704 bytes

__global__ void __launch_bounds__(256, 1)
fused_attn_kernel(const float* __restrict__ conv_feat,
                  const float* __restrict__ trans_feat,
                  float* __restrict__ out)
{
    extern __shared__ float sm[];
    float* feat = sm;
    float4* feat4 = (float4*)sm;                    // stride 17
    ulonglong2* qkvu  = (ulonglong2*)(sm + 8704);   // stride 96 per token
    ulonglong2* wtu   = (ulonglong2*)(sm + 33280);  // stride 33 per c
    ulonglong2* outsu = (ulonglong2*)(sm + 33280);  // stride 33 per token
    ulonglong2* psu   = (ulonglong2*)(sm + 41728);  // stride 33 per channel
    float4* wt4 = (float4*)(sm + 33280);
    float4* ps4 = (float4*)(sm + 41728);

    const int tid = threadIdx.x;
    const int wb = blockIdx.x;
    const int base = ((wb >> 8) * 4) * 4096 + (((wb >> 4) & 15) * 4) * 64 + (wb & 15) * 4;

    // ---- Phase 1: load cf/tf window tiles (channel-major [c][t]) ----
    #pragma unroll
    for (int k = 0; k < 8; k++) {
        int v = k * 256 + tid;              // 0..2047 float4s
        int vv = v & 1023;
        int c = vv >> 4;
        int r16 = vv & 15;                  // (dz,dy)
        const float* src = (v < 1024) ? conv_feat : trans_feat;
        float4 val = *(const float4*)(src + (size_t)c * VOL + base + (r16 >> 2) * 4096 + (r16 & 3) * 64);
        int row = (v < 1024) ? c : (64 + c);
        feat4[row * 17 + r16] = val;
    }
    __syncthreads();

    // ---- Phase 2: qkv[t][o] = sum_c WQKVT[c][o] * feat[c][t] + QB[o] ----
    const int tx = tid & 15;   // token group (4 tokens: t = tx*4+m)
    const int ty = tid >> 4;   // output group (8 outputs: o = ob + ty*8 + r)
    const int sx = tx & 7;     // swizzle key = (t>>2)&7
    const float4* gW4 = (const float4*)g_WQKVT;  // [c][96] float4

    for (int ob = 0; ob < 384; ob += 128) {
        // stage weight chunk: wt4[c*33 + o4] = WQKVT4[c*96 + ob/4 + o4]
        #pragma unroll
        for (int k = 0; k < 16; k++) {
            int f = k * 256 + tid;          // 0..4095
            int c = f >> 5, o4 = f & 31;
            wt4[c * 33 + o4] = gW4[c * 96 + (ob >> 2) + o4];
        }
        __syncthreads();

        // acc[op][m]: op = o-pair (0..3 -> outputs 2op,2op+1), m = token (t=tx*4+m)
        u64 acc[4][4];
        {
            float qb[8];
            #pragma unroll
            for (int r = 0; r < 8; r++) qb[r] = g_QB[ob + ty * 8 + r];
            #pragma unroll
            for (int op = 0; op < 4; op++) {
                u64 b2 = pk2(qb[op * 2], qb[op * 2 + 1]);
                acc[op][0] = b2; acc[op][1] = b2; acc[op][2] = b2; acc[op][3] = b2;
            }
        }
        #pragma unroll 4
        for (int c = 0; c < 128; c++) {
            float4 fv = feat4[c * 17 + tx];
            ulonglong2 wv0 = wtu[c * 33 + ty * 2];       // pairs (o0,o1),(o2,o3)
            ulonglong2 wv1 = wtu[c * 33 + ty * 2 + 1];   // pairs (o4,o5),(o6,o7)
            u64 d0 = pk2(fv.x, fv.x), d1 = pk2(fv.y, fv.y);
            u64 d2 = pk2(fv.z, fv.z), d3 = pk2(fv.w, fv.w);
            fma2(acc[0][0], wv0.x, d0); fma2(acc[0][1], wv0.x, d1);
            fma2(acc[0][2], wv0.x, d2); fma2(acc[0][3], wv0.x, d3);
            fma2(acc[1][0], wv0.y, d0); fma2(acc[1][1], wv0.y, d1);
            fma2(acc[1][2], wv0.y, d2); fma2(acc[1][3], wv0.y, d3);
            fma2(acc[2][0], wv1.x, d0); fma2(acc[2][1], wv1.x, d1);
            fma2(acc[2][2], wv1.x, d2); fma2(acc[2][3], wv1.x, d3);
            fma2(acc[3][0], wv1.y, d0); fma2(acc[3][1], wv1.y, d1);
            fma2(acc[3][2], wv1.y, d2); fma2(acc[3][3], wv1.y, d3);
        }
        // swizzled conflict-free 16B stores along o: float4(o0..o3) = {pair(o0,o1), pair(o2,o3)}
        #pragma unroll
        for (int r4 = 0; r4 < 2; r4++) {
            int u = (ob >> 2) + ty * 2 + r4;  // 16B-unit index within 96
            #pragma unroll
            for (int m = 0; m < 4; m++) {
                int t = tx * 4 + m;
                ulonglong2 st;
                st.x = acc[r4 * 2 + 0][m];
                st.y = acc[r4 * 2 + 1][m];
                qkvu[t * 96 + (u ^ sx)] = st;
            }
        }
        __syncthreads();
    }

    // ---- Phase 3: per-(head,row) attention entirely in registers ----
    {
        const int h = tid >> 6;            // warp-uniform
        const int ii = tid & 63;
        const int isw = (ii >> 2) & 7;
        u64 qvp[16];                       // q pairs along d
        #pragma unroll
        for (int d4 = 0; d4 < 8; d4++) {
            ulonglong2 q = qkvu[ii * 96 + ((h * 8 + d4) ^ isw)];
            qvp[d4 * 2] = q.x; qvp[d4 * 2 + 1] = q.y;
        }
        float sc[64];
        const float4* brow4 = (const float4*)(g_BIAS + (h * 64 + ii) * 64);
        #pragma unroll
        for (int j4 = 0; j4 < 16; j4++) {
            float4 b = brow4[j4];
            sc[j4 * 4 + 0] = b.x; sc[j4 * 4 + 1] = b.y;
            sc[j4 * 4 + 2] = b.z; sc[j4 * 4 + 3] = b.w;
        }
        const float scale = 0.17677669529663688f;  // 32^-0.5
        float rowmax = -1e30f;
        #pragma unroll
        for (int j = 0; j < 64; j++) {
            int jsw = (j >> 2) & 7;
            u64 a0 = 0ull, a1 = 0ull;      // 0x0 == packed {0.f,0.f}
            #pragma unroll
            for (int d4 = 0; d4 < 8; d4++) {
                ulonglong2 kk = qkvu[j * 96 + ((32 + h * 8 + d4) ^ jsw)];  // warp-broadcast
                fma2(a0, qvp[d4 * 2], kk.x);
                fma2(a1, qvp[d4 * 2 + 1], kk.y);
            }
            float l0, h0, l1, h1;
            upk2(a0, l0, h0); upk2(a1, l1, h1);
            float a = (l0 + h0) + (l1 + h1);
            sc[j] = fmaf(a, scale, sc[j]);
            rowmax = fmaxf(rowmax, sc[j]);
        }
        float ssum = 0.f;
        #pragma unroll
        for (int j = 0; j < 64; j++) {
            sc[j] = __expf(sc[j] - rowmax);
            ssum += sc[j];
        }
        float inv = 1.f / ssum;
        u64 ovp[16];
        #pragma unroll
        for (int d = 0; d < 16; d++) ovp[d] = 0ull;
        #pragma unroll
        for (int j = 0; j < 64; j++) {
            int jsw = (j >> 2) & 7;
            u64 p2 = pk2(sc[j], sc[j]);
            #pragma unroll
            for (int d4 = 0; d4 < 8; d4++) {
                ulonglong2 vv = qkvu[j * 96 + ((64 + h * 8 + d4) ^ jsw)];  // warp-broadcast
                fma2(ovp[d4 * 2], p2, vv.x);
                fma2(ovp[d4 * 2 + 1], p2, vv.y);
            }
        }
        u64 inv2 = pk2(inv, inv);
        #pragma unroll
        for (int d4 = 0; d4 < 8; d4++) {
            ulonglong2 st;
            st.x = mul2(ovp[d4 * 2], inv2);
            st.y = mul2(ovp[d4 * 2 + 1], inv2);
            outsu[ii * 33 + h * 8 + d4] = st;
        }
    }

    // stage P tile (ps region disjoint from outs & qkv)
    #pragma unroll
    for (int k = 0; k < 8; k++) {
        int f = k * 256 + tid;              // 0..2047
        ps4[(f >> 5) * 33 + (f & 31)] = *((const float4*)g_P + f);
    }
    __syncthreads();

    // ---- Phase 4: final[t][c] = sum_k outs[t][k]*P[c][k] + PB[c] + conv_feat[c][t] ----
    // token mapping t = m*16 + tx  (lane-consecutive -> conflict-free outs reads)
    // accumulate packed along k; horizontal add at the end
    {
        u64 acc2[4][4];
        #pragma unroll
        for (int r = 0; r < 4; r++)
            #pragma unroll
            for (int m = 0; m < 4; m++) acc2[r][m] = 0ull;

        #pragma unroll 4
        for (int k4 = 0; k4 < 32; k4++) {
            ulonglong2 pr[4], ovv[4];
            #pragma unroll
            for (int r = 0; r < 4; r++) pr[r] = psu[(ty * 4 + r) * 33 + k4];
            #pragma unroll
            for (int m = 0; m < 4; m++) ovv[m] = outsu[(m * 16 + tx) * 33 + k4];
            #pragma unroll
            for (int r = 0; r < 4; r++)
                #pragma unroll
                for (int m = 0; m < 4; m++) {
                    fma2(acc2[r][m], pr[r].x, ovv[m].x);
                    fma2(acc2[r][m], pr[r].y, ovv[m].y);
                }
        }
        int dy = tx >> 2, dx = tx & 3;
        #pragma unroll
        for (int r = 0; r < 4; r++) {
            int c = ty * 4 + r;
            float pb = g_PB[c];
            #pragma unroll
            for (int m = 0; m < 4; m++) {
                int t = m * 16 + tx;
                float lo, hi;
                upk2(acc2[r][m], lo, hi);
                float cf = feat[c * 68 + t];
                out[(size_t)c * VOL + base + m * 4096 + dy * 64 + dx] = (lo + hi) + pb + cf;
            }
        }
    }
}

// ---------------- launch ----------------
extern "C" void kernel_launch(void* const* d_in, const int* in_sizes, int n_in,
                              void* d_out, int out_size)
{
    const float* conv_feat  = (const float*)d_in[0];
    const float* trans_feat = (const float*)d_in[1];
    const float* conv_w     = (const float*)d_in[2];
    const float* conv_b     = (const float*)d_in[3];
    const float* trans_w    = (const float*)d_in[4];
    const float* trans_b    = (const float*)d_in[5];
    const float* qkv_w      = (const float*)d_in[6];
    const float* qkv_b      = (const float*)d_in[7];
    const float* proj_w     = (const float*)d_in[8];
    const float* proj_b     = (const float*)d_in[9];
    const float* table      = (const float*)d_in[10];
    const int*   ridx       = (const int*)d_in[11];
    float* o = (float*)d_out;

    cudaFuncSetAttribute(fused_attn_kernel, cudaFuncAttributeMaxDynamicSharedMemorySize, 200704);

    prep_kernel<<<290, 256>>>(conv_w, conv_b, trans_w, trans_b,
                              qkv_w, qkv_b, proj_w, proj_b, table, ridx);
    fused_attn_kernel<<<4096, 256, 200704>>>(conv_feat, trans_feat, o);
}